// round 1
// baseline (speedup 1.0000x reference)
#include <cuda_runtime.h>
#include <cstdint>

// ---------------------------------------------------------------------------
// BatchTopK: out = scatter(top_{k*rows}(relu(x)))  over the FLATTENED array.
// Strategy: exact radix-select on float bit patterns (positive floats are
// monotonic in their uint32 bit representation).
//   Pass 1: 4096-bin histogram of bits[31:19] of positive values (128MB read)
//   Pass 2: (1 thread) find the 13-bit bucket holding rank n_keep
//   Pass 3: write out = v for bins strictly above bucket, 0 otherwise;
//           collect in-bucket candidates (~50K) to a global list
//           (128MB read + 128MB write, fused)
//   Pass 4: (1 block) refine remaining 19 bits over the candidate list to get
//           the exact 32-bit threshold; emit >T candidates; resolve ==T ties
//           by smallest flat index (matches jax.lax.top_k tie-breaking).
// ---------------------------------------------------------------------------

#define HIST_BINS 4096
#define CAND_CAP  (1u << 20)   // 1M candidates * 8B = 8MB scratch
#define EQ_CAP    2048

__device__ unsigned int       g_hist[HIST_BINS];
__device__ int                g_bucket;      // -1: keep all positives; HIST_BINS: keep none
__device__ unsigned int       g_rem;         // slots remaining inside the bucket
__device__ unsigned int       g_cand_count;
__device__ unsigned long long g_cand[CAND_CAP];  // (bits<<32) | flat_index

// ---------------------------------------------------------------------------
__global__ void init_kernel() {
    int i = blockIdx.x * blockDim.x + threadIdx.x;
    if (i < HIST_BINS) g_hist[i] = 0;
    if (i == 0) { g_cand_count = 0; g_bucket = -2; g_rem = 0; }
}

// ---------------------------------------------------------------------------
__global__ void hist_kernel(const float4* __restrict__ x4, int n4,
                            const float* __restrict__ x, int n) {
    __shared__ unsigned int sh[HIST_BINS];
    for (int i = threadIdx.x; i < HIST_BINS; i += blockDim.x) sh[i] = 0;
    __syncthreads();

    int stride = gridDim.x * blockDim.x;
    for (int i = blockIdx.x * blockDim.x + threadIdx.x; i < n4; i += stride) {
        float4 v = x4[i];
        if (v.x > 0.f) atomicAdd(&sh[__float_as_uint(v.x) >> 19], 1u);
        if (v.y > 0.f) atomicAdd(&sh[__float_as_uint(v.y) >> 19], 1u);
        if (v.z > 0.f) atomicAdd(&sh[__float_as_uint(v.z) >> 19], 1u);
        if (v.w > 0.f) atomicAdd(&sh[__float_as_uint(v.w) >> 19], 1u);
    }
    // tail (n % 4 leftovers) -- only low-numbered global threads can hit this
    int t0 = n4 * 4 + blockIdx.x * blockDim.x + threadIdx.x;
    if (t0 < n) {
        float v = x[t0];
        if (v > 0.f) atomicAdd(&sh[__float_as_uint(v) >> 19], 1u);
    }
    __syncthreads();
    for (int i = threadIdx.x; i < HIST_BINS; i += blockDim.x) {
        unsigned c = sh[i];
        if (c) atomicAdd(&g_hist[i], c);
    }
}

// ---------------------------------------------------------------------------
__global__ void select_kernel(const int* __restrict__ kptr, long long num_samples) {
    if (threadIdx.x != 0 || blockIdx.x != 0) return;
    long long n_keep = (long long)kptr[0] * num_samples;
    if (n_keep <= 0) { g_bucket = HIST_BINS; g_rem = 0; return; }
    long long cum = 0;
    for (int i = HIST_BINS - 1; i >= 0; --i) {
        unsigned c = g_hist[i];
        if (cum + (long long)c >= n_keep) {
            g_bucket = i;
            g_rem = (unsigned)(n_keep - cum);
            return;
        }
        cum += c;
    }
    g_bucket = -1;  // fewer positives than n_keep: keep every positive value
    g_rem = 0;
}

// ---------------------------------------------------------------------------
__device__ __forceinline__ float classify(float c, int bucket, unsigned gidx) {
    if (c > 0.f) {
        unsigned u = __float_as_uint(c);
        int bin = (int)(u >> 19);
        if (bucket == -1 || bin > bucket) return c;
        if (bin == bucket) {
            unsigned p = atomicAdd(&g_cand_count, 1u);
            if (p < CAND_CAP)
                g_cand[p] = ((unsigned long long)u << 32) | (unsigned long long)gidx;
        }
    }
    return 0.f;
}

__global__ void write_kernel(const float4* __restrict__ x4, float4* __restrict__ o4, int n4,
                             const float* __restrict__ x, float* __restrict__ o, int n) {
    int bucket = g_bucket;
    int i = blockIdx.x * blockDim.x + threadIdx.x;
    if (i < n4) {
        float4 v = x4[i];
        float4 r;
        unsigned base = (unsigned)i * 4u;
        r.x = classify(v.x, bucket, base + 0u);
        r.y = classify(v.y, bucket, base + 1u);
        r.z = classify(v.z, bucket, base + 2u);
        r.w = classify(v.w, bucket, base + 3u);
        o4[i] = r;
    }
    int t0 = n4 * 4 + i;
    if (t0 < n) {
        o[t0] = classify(x[t0], bucket, (unsigned)t0);
    }
}

// ---------------------------------------------------------------------------
__global__ void refine_kernel(float* __restrict__ out) {
    __shared__ unsigned int sh[8192];
    __shared__ unsigned int eqidx[EQ_CAP];
    __shared__ unsigned int s_b1, s_r1, s_b2, s_r2, s_eqc;

    int bucket = g_bucket;
    if (bucket < 0 || bucket >= HIST_BINS) return;  // keep-all / keep-none handled already

    unsigned m = min(g_cand_count, CAND_CAP);
    unsigned r = g_rem;
    int tid = threadIdx.x;

    // --- refine bits [18:6] (8192 bins) over candidate list ---
    for (int i = tid; i < 8192; i += blockDim.x) sh[i] = 0;
    __syncthreads();
    for (unsigned i = tid; i < m; i += blockDim.x) {
        unsigned u = (unsigned)(g_cand[i] >> 32);
        atomicAdd(&sh[(u >> 6) & 0x1FFFu], 1u);
    }
    __syncthreads();
    if (tid == 0) {
        unsigned long long cum = 0; unsigned rr = r; unsigned b1 = 0;
        for (int i = 8191; i >= 0; --i) {
            unsigned c = sh[i];
            if (cum + c >= rr) { b1 = (unsigned)i; rr -= (unsigned)cum; break; }
            cum += c;
        }
        s_b1 = b1; s_r1 = rr;
    }
    __syncthreads();
    unsigned b1 = s_b1, r1 = s_r1;

    // --- refine bits [5:0] (64 bins) ---
    for (int i = tid; i < 64; i += blockDim.x) sh[i] = 0;
    __syncthreads();
    for (unsigned i = tid; i < m; i += blockDim.x) {
        unsigned u = (unsigned)(g_cand[i] >> 32);
        if (((u >> 6) & 0x1FFFu) == b1) atomicAdd(&sh[u & 0x3Fu], 1u);
    }
    __syncthreads();
    if (tid == 0) {
        unsigned cum = 0, rr = r1, b2 = 0;
        for (int i = 63; i >= 0; --i) {
            unsigned c = sh[i];
            if (cum + c >= rr) { b2 = (unsigned)i; rr -= cum; break; }
            cum += c;
        }
        s_b2 = b2; s_r2 = rr; s_eqc = 0;
    }
    __syncthreads();
    unsigned b2 = s_b2, r2 = s_r2;
    unsigned T = ((unsigned)bucket << 19) | (b1 << 6) | b2;  // exact 32-bit threshold

    // --- emit > T, gather == T ties ---
    for (unsigned i = tid; i < m; i += blockDim.x) {
        unsigned long long cv = g_cand[i];
        unsigned u   = (unsigned)(cv >> 32);
        unsigned idx = (unsigned)cv;
        if (u > T) {
            out[idx] = __uint_as_float(u);
        } else if (u == T) {
            unsigned p = atomicAdd(&s_eqc, 1u);
            if (p < EQ_CAP) eqidx[p] = idx;
        }
    }
    __syncthreads();

    // --- ties: keep the r2 SMALLEST flat indices (jax top_k tie order) ---
    unsigned ec = min(s_eqc, (unsigned)EQ_CAP);
    for (unsigned t = tid; t < ec; t += blockDim.x) {
        unsigned my = eqidx[t];
        unsigned rank = 0;
        for (unsigned j = 0; j < ec; ++j)
            if (eqidx[j] < my) rank++;
        if (rank < r2) out[my] = __uint_as_float(T);
    }
}

// ---------------------------------------------------------------------------
extern "C" void kernel_launch(void* const* d_in, const int* in_sizes, int n_in,
                              void* d_out, int out_size) {
    const float* x  = (const float*)d_in[0];
    const int*   kp = (const int*)d_in[1];
    int n = in_sizes[0];
    long long num_samples = (long long)n / 16384;  // product of leading dims (last dim = 16384)
    int n4 = n / 4;

    init_kernel<<<(HIST_BINS + 255) / 256, 256>>>();

    int hist_blocks = 148 * 8;  // one full wave at 8 blocks/SM (16KB smem each)
    hist_kernel<<<hist_blocks, 256>>>((const float4*)x, n4, x, n);

    select_kernel<<<1, 32>>>(kp, num_samples);

    int wb = (n4 + 255) / 256;
    if (wb < 1) wb = 1;
    write_kernel<<<wb, 256>>>((const float4*)x, (float4*)d_out, n4,
                              x, (float*)d_out, n);

    refine_kernel<<<1, 1024>>>((float*)d_out);
}

// round 3
// speedup vs baseline: 2.9627x; 2.9627x over previous
#include <cuda_runtime.h>

// ---------------------------------------------------------------------------
// BatchTopK: out = scatter(top_{k*rows}(relu(x))) over the FLATTENED array.
// Exact radix-select on float bits. R2: sampling prepass picks a conservative
// lower bound so the main histogram only does atomics for ~0.4-3% of elements
// (R1 showed shared-atomic throughput, not bandwidth, dominated). Serial bin
// scans replaced by 1024-thread suffix scans. Fallback kernels guarantee
// exactness if the sampled bound is too aggressive.
// ---------------------------------------------------------------------------

#define HIST_BINS 4096
#define CAND_CAP  (1u << 21)   // 2M candidates * 8B = 16MB scratch
#define EQ_CAP    2048
#define SSTR4     128          // sample every 128th float4 (1/128 of elements)

__device__ unsigned int       g_shist[HIST_BINS];   // sampled histogram
__device__ unsigned int       g_hist[HIST_BINS];    // exact histogram (bins >= lbin)
__device__ unsigned int       g_lbin;               // conservative lower-bound bin
__device__ int                g_bucket;             // -1 keep all positives; HIST_BINS keep none
__device__ unsigned int       g_rem;                // slots remaining inside bucket
__device__ int                g_need_full;          // sampled bound was too high
__device__ unsigned int       g_cand_count;
__device__ unsigned long long g_cand[CAND_CAP];     // (bits<<32) | flat_index

// ---------------------------------------------------------------------------
__global__ void init_kernel() {
    int i = blockIdx.x * blockDim.x + threadIdx.x;
    if (i < HIST_BINS) { g_shist[i] = 0; g_hist[i] = 0; }
    if (i == 0) {
        g_cand_count = 0; g_bucket = -2; g_rem = 0;
        g_need_full = 0; g_lbin = 0;
    }
}

// ---------------------------------------------------------------------------
__global__ void sample_kernel(const float4* __restrict__ x4, int n4) {
    __shared__ unsigned int sh[HIST_BINS];
    for (int i = threadIdx.x; i < HIST_BINS; i += blockDim.x) sh[i] = 0;
    __syncthreads();
    int ns = n4 / SSTR4;
    int stride = gridDim.x * blockDim.x;
    for (int j = blockIdx.x * blockDim.x + threadIdx.x; j < ns; j += stride) {
        float4 v = x4[(size_t)j * SSTR4];
        if (v.x > 0.f) atomicAdd(&sh[__float_as_uint(v.x) >> 19], 1u);
        if (v.y > 0.f) atomicAdd(&sh[__float_as_uint(v.y) >> 19], 1u);
        if (v.z > 0.f) atomicAdd(&sh[__float_as_uint(v.z) >> 19], 1u);
        if (v.w > 0.f) atomicAdd(&sh[__float_as_uint(v.w) >> 19], 1u);
    }
    __syncthreads();
    for (int i = threadIdx.x; i < HIST_BINS; i += blockDim.x) {
        unsigned c = sh[i];
        if (c) atomicAdd(&g_shist[i], c);
    }
}

// ---------------------------------------------------------------------------
// Pick lbin = largest bin whose sampled suffix count >= ~8x the scaled n_keep.
__global__ void choose_kernel(const int* __restrict__ kptr, long long num_samples,
                              int n, int n4) {
    __shared__ unsigned int ssum[1024];
    int t = threadIdx.x;
    unsigned c[4];
#pragma unroll
    for (int q = 0; q < 4; q++) c[q] = g_shist[4 * t + q];
    unsigned my = c[0] + c[1] + c[2] + c[3];
    ssum[t] = my;
    __syncthreads();
    for (int d = 1; d < 1024; d <<= 1) {
        unsigned v = ssum[t] + ((t + d < 1024) ? ssum[t + d] : 0u);
        __syncthreads();
        ssum[t] = v;
        __syncthreads();
    }
    long long n_keep = (long long)kptr[0] * num_samples;
    long long sampled = (long long)(n4 / SSTR4) * 4;
    if (sampled < 1) sampled = 1;
    long long scale = ((long long)n + sampled - 1) / sampled;
    if (scale < 1) scale = 1;
    long long tgt = (8 * n_keep) / scale;
    if (tgt < 512) tgt = 512;
    unsigned target = (tgt > 0x7FFFFFFFLL) ? 0x7FFFFFFFu : (unsigned)tgt;

    unsigned S_after = ssum[t] - my;   // sampled count strictly above my bin range
    if (S_after < target && S_after + my >= target) {
        unsigned cum = S_after;
        for (int b = 4 * t + 3; b >= 4 * t; --b) {
            unsigned cc = c[b - 4 * t];
            if (cum + cc >= target) { g_lbin = (unsigned)b; break; }
            cum += cc;
        }
    }
    // if no crossing (few positives), g_lbin stays 0 -> full histogram path
}

// ---------------------------------------------------------------------------
__global__ void hist_kernel(const float4* __restrict__ x4, int n4,
                            const float* __restrict__ x, int n) {
    __shared__ unsigned int sh[HIST_BINS];
    for (int i = threadIdx.x; i < HIST_BINS; i += blockDim.x) sh[i] = 0;
    __syncthreads();
    unsigned lbits = g_lbin << 19;
    int stride = gridDim.x * blockDim.x;
    for (int i = blockIdx.x * blockDim.x + threadIdx.x; i < n4; i += stride) {
        float4 v = x4[i];
        unsigned ux = __float_as_uint(v.x);
        unsigned uy = __float_as_uint(v.y);
        unsigned uz = __float_as_uint(v.z);
        unsigned uw = __float_as_uint(v.w);
        if (v.x > 0.f && ux >= lbits) atomicAdd(&sh[ux >> 19], 1u);
        if (v.y > 0.f && uy >= lbits) atomicAdd(&sh[uy >> 19], 1u);
        if (v.z > 0.f && uz >= lbits) atomicAdd(&sh[uz >> 19], 1u);
        if (v.w > 0.f && uw >= lbits) atomicAdd(&sh[uw >> 19], 1u);
    }
    int t0 = n4 * 4 + blockIdx.x * blockDim.x + threadIdx.x;
    if (t0 < n) {
        float v = x[t0];
        unsigned u = __float_as_uint(v);
        if (v > 0.f && u >= lbits) atomicAdd(&sh[u >> 19], 1u);
    }
    __syncthreads();
    for (int i = threadIdx.x; i < HIST_BINS; i += blockDim.x) {
        unsigned c = sh[i];
        if (c) atomicAdd(&g_hist[i], c);
    }
}

// ---------------------------------------------------------------------------
// Fallback: complete the histogram for bins < lbin. No-op unless need_full.
__global__ void fixup_kernel(const float4* __restrict__ x4, int n4,
                             const float* __restrict__ x, int n) {
    if (!g_need_full) return;
    __shared__ unsigned int sh[HIST_BINS];
    for (int i = threadIdx.x; i < HIST_BINS; i += blockDim.x) sh[i] = 0;
    __syncthreads();
    unsigned lbits = g_lbin << 19;
    int stride = gridDim.x * blockDim.x;
    for (int i = blockIdx.x * blockDim.x + threadIdx.x; i < n4; i += stride) {
        float4 v = x4[i];
        unsigned ux = __float_as_uint(v.x);
        unsigned uy = __float_as_uint(v.y);
        unsigned uz = __float_as_uint(v.z);
        unsigned uw = __float_as_uint(v.w);
        if (v.x > 0.f && ux < lbits) atomicAdd(&sh[ux >> 19], 1u);
        if (v.y > 0.f && uy < lbits) atomicAdd(&sh[uy >> 19], 1u);
        if (v.z > 0.f && uz < lbits) atomicAdd(&sh[uz >> 19], 1u);
        if (v.w > 0.f && uw < lbits) atomicAdd(&sh[uw >> 19], 1u);
    }
    int t0 = n4 * 4 + blockIdx.x * blockDim.x + threadIdx.x;
    if (t0 < n) {
        float v = x[t0];
        unsigned u = __float_as_uint(v);
        if (v > 0.f && u < lbits) atomicAdd(&sh[u >> 19], 1u);
    }
    __syncthreads();
    for (int i = threadIdx.x; i < HIST_BINS; i += blockDim.x) {
        unsigned c = sh[i];
        if (c) atomicAdd(&g_hist[i], c);
    }
}

// ---------------------------------------------------------------------------
// mode 0: after main hist. mode 1: after fixup (runs only if need_full).
__global__ void select_kernel(const int* __restrict__ kptr, long long num_samples,
                              int mode) {
    if (mode == 1 && !g_need_full) return;   // uniform branch
    __shared__ unsigned int ssum[1024];
    int t = threadIdx.x;
    long long n_keep = (long long)kptr[0] * num_samples;
    if (n_keep <= 0) {
        if (t == 0) { g_bucket = HIST_BINS; g_rem = 0; }
        return;                               // uniform branch
    }
    unsigned c[4];
#pragma unroll
    for (int q = 0; q < 4; q++) c[q] = g_hist[4 * t + q];
    unsigned my = c[0] + c[1] + c[2] + c[3];
    ssum[t] = my;
    __syncthreads();
    for (int d = 1; d < 1024; d <<= 1) {
        unsigned v = ssum[t] + ((t + d < 1024) ? ssum[t + d] : 0u);
        __syncthreads();
        ssum[t] = v;
        __syncthreads();
    }
    unsigned total = ssum[0];
    unsigned S_after = ssum[t] - my;
    if ((long long)total < n_keep) {
        if (t == 0) {
            if (mode == 0) {
                if (g_lbin == 0u) { g_bucket = -1; g_rem = 0; } // full hist, keep all positives
                else              { g_need_full = 1; }          // bound too high, redo
            } else {
                g_bucket = -1; g_rem = 0;                       // complete hist, still short
            }
        }
        return;
    }
    if ((long long)S_after < n_keep && (long long)S_after + (long long)my >= n_keep) {
        unsigned cum = S_after;
        for (int b = 4 * t + 3; b >= 4 * t; --b) {
            unsigned cc = c[b - 4 * t];
            if ((long long)cum + (long long)cc >= n_keep) {
                g_bucket = b;
                g_rem = (unsigned)(n_keep - (long long)cum);
                break;
            }
            cum += cc;
        }
    }
}

// ---------------------------------------------------------------------------
__device__ __forceinline__ float classify(float v, int bucket, unsigned gidx) {
    if (v > 0.f) {
        unsigned u = __float_as_uint(v);
        int bin = (int)(u >> 19);
        if (bucket == -1 || bin > bucket) return v;
        if (bin == bucket) {
            unsigned p = atomicAdd(&g_cand_count, 1u);
            if (p < CAND_CAP)
                g_cand[p] = ((unsigned long long)u << 32) | (unsigned long long)gidx;
        }
    }
    return 0.f;
}

__global__ void write_kernel(const float4* __restrict__ x4, float4* __restrict__ o4, int n4,
                             const float* __restrict__ x, float* __restrict__ o, int n) {
    int bucket = g_bucket;
    // Reverse block order: hist left the TAIL of x resident in L2, so reading
    // back-to-front maximizes L2 hits. Evict-first stores protect x in L2.
    int chunk = (int)(gridDim.x - 1u - blockIdx.x);
    int i = chunk * blockDim.x + threadIdx.x;
    if (i < n4) {
        float4 v = x4[i];
        float4 r;
        unsigned base = (unsigned)i * 4u;
        r.x = classify(v.x, bucket, base + 0u);
        r.y = classify(v.y, bucket, base + 1u);
        r.z = classify(v.z, bucket, base + 2u);
        r.w = classify(v.w, bucket, base + 3u);
        __stcs(&o4[i], r);
    }
    int t0 = n4 * 4 + blockIdx.x * blockDim.x + threadIdx.x;
    if (t0 < n) {
        o[t0] = classify(x[t0], bucket, (unsigned)t0);
    }
}

// ---------------------------------------------------------------------------
__global__ void refine_kernel(float* __restrict__ out) {
    __shared__ unsigned int sh[8192];
    __shared__ unsigned int ssum[1024];
    __shared__ unsigned int eqidx[EQ_CAP];
    __shared__ unsigned int s_b1, s_r1, s_b2, s_r2, s_eqc;

    int bucket = g_bucket;
    if (bucket < 0 || bucket >= HIST_BINS) return;  // keep-all / keep-none done

    unsigned m = min(g_cand_count, CAND_CAP);
    unsigned r = g_rem;
    int tid = threadIdx.x;

    // --- histogram bits [18:6] (8192 bins) over candidate list ---
    for (int i = tid; i < 8192; i += blockDim.x) sh[i] = 0;
    __syncthreads();
    for (unsigned i = tid; i < m; i += blockDim.x) {
        unsigned u = (unsigned)(g_cand[i] >> 32);
        atomicAdd(&sh[(u >> 6) & 0x1FFFu], 1u);
    }
    __syncthreads();

    // --- parallel suffix scan to find bucket b1 holding rank r ---
    unsigned c8[8];
#pragma unroll
    for (int q = 0; q < 8; q++) c8[q] = sh[8 * tid + q];
    unsigned my = 0;
#pragma unroll
    for (int q = 0; q < 8; q++) my += c8[q];
    ssum[tid] = my;
    __syncthreads();
    for (int d = 1; d < 1024; d <<= 1) {
        unsigned v = ssum[tid] + ((tid + d < 1024) ? ssum[tid + d] : 0u);
        __syncthreads();
        ssum[tid] = v;
        __syncthreads();
    }
    unsigned S_after = ssum[tid] - my;
    if (S_after < r && S_after + my >= r) {
        unsigned cum = S_after;
        for (int b = 8 * tid + 7; b >= 8 * tid; --b) {
            unsigned cc = c8[b - 8 * tid];
            if (cum + cc >= r) { s_b1 = (unsigned)b; s_r1 = r - cum; break; }
            cum += cc;
        }
    }
    __syncthreads();
    unsigned b1 = s_b1, r1 = s_r1;

    // --- refine bits [5:0] (64 bins) ---
    for (int i = tid; i < 64; i += blockDim.x) sh[i] = 0;
    __syncthreads();
    for (unsigned i = tid; i < m; i += blockDim.x) {
        unsigned u = (unsigned)(g_cand[i] >> 32);
        if (((u >> 6) & 0x1FFFu) == b1) atomicAdd(&sh[u & 0x3Fu], 1u);
    }
    __syncthreads();
    if (tid == 0) {
        unsigned cum = 0, rr = r1, b2 = 0;
        for (int i = 63; i >= 0; --i) {
            unsigned cc = sh[i];
            if (cum + cc >= rr) { b2 = (unsigned)i; rr -= cum; break; }
            cum += cc;
        }
        s_b2 = b2; s_r2 = rr; s_eqc = 0;
    }
    __syncthreads();
    unsigned b2 = s_b2, r2 = s_r2;
    unsigned T = ((unsigned)bucket << 19) | (b1 << 6) | b2;  // exact 32-bit threshold

    // --- emit > T, gather == T ties ---
    for (unsigned i = tid; i < m; i += blockDim.x) {
        unsigned long long cv = g_cand[i];
        unsigned u   = (unsigned)(cv >> 32);
        unsigned idx = (unsigned)cv;
        if (u > T) {
            out[idx] = __uint_as_float(u);
        } else if (u == T) {
            unsigned p = atomicAdd(&s_eqc, 1u);
            if (p < EQ_CAP) eqidx[p] = idx;
        }
    }
    __syncthreads();

    // --- ties: keep the r2 SMALLEST flat indices (jax top_k tie order) ---
    unsigned ec = min(s_eqc, (unsigned)EQ_CAP);
    for (unsigned t = tid; t < ec; t += blockDim.x) {
        unsigned myi = eqidx[t];
        unsigned rank = 0;
        for (unsigned j = 0; j < ec; ++j)
            if (eqidx[j] < myi) rank++;
        if (rank < r2) out[myi] = __uint_as_float(T);
    }
}

// ---------------------------------------------------------------------------
extern "C" void kernel_launch(void* const* d_in, const int* in_sizes, int n_in,
                              void* d_out, int out_size) {
    const float* x  = (const float*)d_in[0];
    const int*   kp = (const int*)d_in[1];
    int n = in_sizes[0];
    long long num_samples = (long long)n / 16384;  // last dim = 16384
    int n4 = n / 4;

    init_kernel<<<(HIST_BINS + 255) / 256, 256>>>();

    sample_kernel<<<64, 256>>>((const float4*)x, n4);
    choose_kernel<<<1, 1024>>>(kp, num_samples, n, n4);

    int hist_blocks = 148 * 8;
    hist_kernel<<<hist_blocks, 256>>>((const float4*)x, n4, x, n);

    select_kernel<<<1, 1024>>>(kp, num_samples, 0);
    fixup_kernel<<<hist_blocks, 256>>>((const float4*)x, n4, x, n);
    select_kernel<<<1, 1024>>>(kp, num_samples, 1);

    int wb = (n4 + 255) / 256;
    if (wb < 1) wb = 1;
    write_kernel<<<wb, 256>>>((const float4*)x, (float4*)d_out, n4,
                              x, (float*)d_out, n);

    refine_kernel<<<1, 1024>>>((float*)d_out);
}